// round 4
// baseline (speedup 1.0000x reference)
#include <cuda_runtime.h>
#include <math.h>
#include <stdint.h>

#define BATCH 64
#define SEQ   512
#define DM    512
#define NH    8
#define HD    64
#define NA    32
#define WIN   64
#define FF    2048
#define MROWS (BATCH*SEQ)     // 32768
#define MAROWS (BATCH*NA)     // 2048

// ---------------- scratch ----------------
__device__ float g_qkv[(size_t)MROWS * 3 * DM];
__device__ float g_attn[(size_t)MROWS * DM];
__device__ float g_x1 [(size_t)MROWS * DM];
__device__ float g_q2 [(size_t)MROWS * DM];
__device__ float g_kv2[(size_t)MAROWS * 2 * DM];
__device__ float g_x2 [(size_t)MROWS * DM];
__device__ float g_x3 [(size_t)MROWS * DM];
__device__ float g_h  [(size_t)MROWS * FF];
// tf32-rounded + k-permuted weights, packed
#define SZ_LWIN  786432
#define SZ_LWOUT 262144
#define SZ_GWIN  786432
#define SZ_GWOUT 262144
#define SZ_W1    1048576
#define SZ_W2    1048576
#define OFF_LWIN  0
#define OFF_LWOUT (OFF_LWIN + SZ_LWIN)
#define OFF_GWIN  (OFF_LWOUT + SZ_LWOUT)
#define OFF_GWOUT (OFF_GWIN + SZ_GWIN)
#define OFF_W1    (OFF_GWOUT + SZ_GWOUT)
#define OFF_W2    (OFF_W1 + SZ_W1)
#define WTF_TOTAL (OFF_W2 + SZ_W2)   // 4,194,304 floats
__device__ float g_wtf[(size_t)WTF_TOTAL];

// ================= helpers =================
__device__ __forceinline__ uint32_t smem_u32(const void* p) {
    uint32_t a;
    asm("{ .reg .u64 t; cvta.to.shared.u64 t, %1; cvt.u32.u64 %0, t; }" : "=r"(a) : "l"(p));
    return a;
}
__device__ __forceinline__ uint32_t f2tf(float x) {
    uint32_t r;
    asm("cvt.rna.tf32.f32 %0, %1;" : "=r"(r) : "f"(x));
    return r;
}
__device__ __forceinline__ void mma8(float* c, const uint32_t* a, const uint32_t* b) {
    asm volatile(
        "mma.sync.aligned.m16n8k8.row.col.f32.tf32.tf32.f32 "
        "{%0,%1,%2,%3}, {%4,%5,%6,%7}, {%8,%9}, {%0,%1,%2,%3};"
        : "+f"(c[0]), "+f"(c[1]), "+f"(c[2]), "+f"(c[3])
        : "r"(a[0]), "r"(a[1]), "r"(a[2]), "r"(a[3]),
          "r"(b[0]), "r"(b[1]));
}
#define CP_ASYNC16(dst, src) \
    asm volatile("cp.async.cg.shared.global [%0], [%1], 16;" :: "r"(dst), "l"(src) : "memory")
#define CP_COMMIT() asm volatile("cp.async.commit_group;" ::: "memory")
#define CP_WAIT0()  asm volatile("cp.async.wait_group 0;" ::: "memory")

// ---------------- weight tf32 + k-permute pre-convert (single launch) --------
// perm within each 8-group: pos(k) = 2*(k&3) + ((k>>2)&1)
__global__ __launch_bounds__(256)
void cvt_all(const float* __restrict__ lw_in, const float* __restrict__ lw_out,
             const float* __restrict__ gw_in, const float* __restrict__ gw_out,
             const float* __restrict__ w1, const float* __restrict__ w2,
             float* __restrict__ dst)
{
    int i = blockIdx.x * 256 + threadIdx.x;
    if (i >= WTF_TOTAL) return;
    const float* src;
    int local, off;
    if      (i < OFF_LWOUT) { src = lw_in;  local = i - OFF_LWIN;  off = OFF_LWIN; }
    else if (i < OFF_GWIN)  { src = lw_out; local = i - OFF_LWOUT; off = OFF_LWOUT; }
    else if (i < OFF_GWOUT) { src = gw_in;  local = i - OFF_GWIN;  off = OFF_GWIN; }
    else if (i < OFF_W1)    { src = gw_out; local = i - OFF_GWOUT; off = OFF_GWOUT; }
    else if (i < OFF_W2)    { src = w1;     local = i - OFF_W1;    off = OFF_W1; }
    else                    { src = w2;     local = i - OFF_W2;    off = OFF_W2; }
    int p = (local & ~7) + 2 * (local & 3) + ((local >> 2) & 1);
    dst[off + p] = __uint_as_float(f2tf(src[local]));
}

// ================= tf32 mma.sync GEMM =================
// C[M,N] = A[M,K] @ W[N,K]^T (+bias)(+res)(gelu)
// CTA 128(M) x 256(N), BK=32, 256 threads, warp tile 64x64 (2x4 warps).
// Smem K-layout is pair-permuted so fragment loads are LDS.64, ASTRIDE=40
// (conflict-free per half-warp phase).
#define ASTRIDE 40
#define A_TILE_F (128 * ASTRIDE)   // 5120 floats
#define B_TILE_F (256 * ASTRIDE)   // 10240 floats
#define GEMM_SMEM_F (2 * A_TILE_F + 2 * B_TILE_F)   // 30720 floats = 120KB

template<bool GELU>
__global__ __launch_bounds__(256)
void gemm_mma(const float* __restrict__ A, const float* __restrict__ W,
              const float* __restrict__ bias, const float* __restrict__ res,
              float* __restrict__ C, int M, int N, int K)
{
    extern __shared__ float sm[];
    float* As[2] = { sm, sm + A_TILE_F };
    float* Bs[2] = { sm + 2 * A_TILE_F, sm + 2 * A_TILE_F + B_TILE_F };

    const int t = threadIdx.x;
    const int wid = t >> 5, lane = t & 31;
    const int gid = lane >> 2, tig = lane & 3;
    const int wm = wid >> 2;            // 0..1
    const int wn = wid & 3;             // 0..3
    const int bm = blockIdx.y * 128;
    const int bn = blockIdx.x * 256;

    const int ar = t >> 3;              // 0..31
    const int ac = (t & 7) << 2;        // 0,4,..,28
    const int aoff = (ac >> 3) * 8 + ((ac & 4) ? 1 : 0);   // permuted base pos

    const float* Abase = A + (size_t)(bm + ar) * K + ac;
    const float* Wbase = W + (size_t)(bn + ar) * K + ac;

    float acc[4][8][4];
#pragma unroll
    for (int i = 0; i < 4; i++)
#pragma unroll
        for (int j = 0; j < 8; j++)
#pragma unroll
            for (int q = 0; q < 4; q++) acc[i][j][q] = 0.f;

    const int KT = K >> 5;

    // ---- prologue: tile 0 ----
    {
        float4 av[4];
#pragma unroll
        for (int i = 0; i < 4; i++)
            av[i] = *(const float4*)(Abase + (size_t)(i * 32) * K);
        uint32_t bdst = smem_u32(Bs[0]) + (uint32_t)(ar * ASTRIDE + ac) * 4u;
#pragma unroll
        for (int i = 0; i < 8; i++)
            CP_ASYNC16(bdst + (uint32_t)(i * 32 * ASTRIDE * 4), Wbase + (size_t)(i * 32) * K);
        CP_COMMIT();
#pragma unroll
        for (int i = 0; i < 4; i++) {
            float* d = As[0] + (ar + i * 32) * ASTRIDE + aoff;
            d[0] = __uint_as_float(f2tf(av[i].x));
            d[2] = __uint_as_float(f2tf(av[i].y));
            d[4] = __uint_as_float(f2tf(av[i].z));
            d[6] = __uint_as_float(f2tf(av[i].w));
        }
        CP_WAIT0();
        __syncthreads();
    }

    for (int kt = 0; kt < KT; kt++) {
        const int buf = kt & 1;
        const bool more = (kt + 1) < KT;
        float4 av[4];
        if (more) {
            const float* Ap = Abase + (size_t)(kt + 1) * 32;
            const float* Wp = Wbase + (size_t)(kt + 1) * 32;
#pragma unroll
            for (int i = 0; i < 4; i++)
                av[i] = *(const float4*)(Ap + (size_t)(i * 32) * K);
            uint32_t bdst = smem_u32(Bs[buf ^ 1]) + (uint32_t)(ar * ASTRIDE + ac) * 4u;
#pragma unroll
            for (int i = 0; i < 8; i++)
                CP_ASYNC16(bdst + (uint32_t)(i * 32 * ASTRIDE * 4), Wp + (size_t)(i * 32) * K);
            CP_COMMIT();
        }

        const float* Ab = As[buf];
        const float* Bb = Bs[buf];
#pragma unroll
        for (int kk = 0; kk < 4; kk++) {
            uint32_t a[4][4], b[8][2];
#pragma unroll
            for (int i = 0; i < 4; i++) {
                int m = wm * 64 + i * 16 + gid;
                float2 p0 = *(const float2*)(Ab + m * ASTRIDE + kk * 8 + 2 * tig);
                float2 p1 = *(const float2*)(Ab + (m + 8) * ASTRIDE + kk * 8 + 2 * tig);
                a[i][0] = __float_as_uint(p0.x); a[i][2] = __float_as_uint(p0.y);
                a[i][1] = __float_as_uint(p1.x); a[i][3] = __float_as_uint(p1.y);
            }
#pragma unroll
            for (int j = 0; j < 8; j++) {
                int n = wn * 64 + j * 8 + gid;
                float2 p = *(const float2*)(Bb + n * ASTRIDE + kk * 8 + 2 * tig);
                b[j][0] = __float_as_uint(p.x); b[j][1] = __float_as_uint(p.y);
            }
#pragma unroll
            for (int i = 0; i < 4; i++)
#pragma unroll
                for (int j = 0; j < 8; j++)
                    mma8(acc[i][j], a[i], b[j]);
        }

        if (more) {
#pragma unroll
            for (int i = 0; i < 4; i++) {
                float* d = As[buf ^ 1] + (ar + i * 32) * ASTRIDE + aoff;
                d[0] = __uint_as_float(f2tf(av[i].x));
                d[2] = __uint_as_float(f2tf(av[i].y));
                d[4] = __uint_as_float(f2tf(av[i].z));
                d[6] = __uint_as_float(f2tf(av[i].w));
            }
            CP_WAIT0();
        }
        __syncthreads();
    }

    // ---- epilogue ----
#pragma unroll
    for (int j = 0; j < 8; j++) {
        const int gc = bn + wn * 64 + j * 8 + 2 * tig;
        const float2 bia = *(const float2*)(bias + gc);
#pragma unroll
        for (int i = 0; i < 4; i++) {
            const int gr = bm + wm * 64 + i * 16 + gid;
            float2 v0, v1;
            v0.x = acc[i][j][0] + bia.x; v0.y = acc[i][j][1] + bia.y;
            v1.x = acc[i][j][2] + bia.x; v1.y = acc[i][j][3] + bia.y;
            if (res) {
                float2 r0 = *(const float2*)(res + (size_t)gr * N + gc);
                float2 r1 = *(const float2*)(res + (size_t)(gr + 8) * N + gc);
                v0.x += r0.x; v0.y += r0.y; v1.x += r1.x; v1.y += r1.y;
            }
            if (GELU) {
                v0.x = 0.5f * v0.x * (1.0f + erff(v0.x * 0.70710678118654752f));
                v0.y = 0.5f * v0.y * (1.0f + erff(v0.y * 0.70710678118654752f));
                v1.x = 0.5f * v1.x * (1.0f + erff(v1.x * 0.70710678118654752f));
                v1.y = 0.5f * v1.y * (1.0f + erff(v1.y * 0.70710678118654752f));
            }
            *(float2*)(C + (size_t)gr * N + gc) = v0;
            *(float2*)(C + (size_t)(gr + 8) * N + gc) = v1;
        }
    }
}

// ---------------- local windowed causal attention ----------------
__global__ __launch_bounds__(256)
void local_attn_kernel(const float* __restrict__ qkv, float* __restrict__ out)
{
    extern __shared__ float sml[];
    float* Qs = sml;
    float* Ks = Qs + 64 * 65;
    float* Vs = Ks + 128 * 65;
    float* Pb = Vs + 128 * 65;

    const int qt = blockIdx.x, h = blockIdx.y, b = blockIdx.z;
    const int t = threadIdx.x;
    const int q0 = qt * 64;
    const int kbase = q0 - 64;

    for (int idx = t; idx < 64 * 16; idx += 256) {
        int r = idx >> 4, c4 = (idx & 15) << 2;
        float4 v = *(const float4*)(qkv + ((size_t)(b*SEQ + q0 + r)) * (3*DM) + h*HD + c4);
        Qs[r*65+c4] = v.x; Qs[r*65+c4+1] = v.y; Qs[r*65+c4+2] = v.z; Qs[r*65+c4+3] = v.w;
    }
    for (int idx = t; idx < 128 * 16; idx += 256) {
        int r = idx >> 4, c4 = (idx & 15) << 2;
        int j = kbase + r;
        if (j >= 0) {
            const float* base = qkv + ((size_t)(b*SEQ + j)) * (3*DM) + DM + h*HD + c4;
            float4 kv = *(const float4*)base;
            float4 vv = *(const float4*)(base + DM);
            Ks[r*65+c4] = kv.x; Ks[r*65+c4+1] = kv.y; Ks[r*65+c4+2] = kv.z; Ks[r*65+c4+3] = kv.w;
            Vs[r*65+c4] = vv.x; Vs[r*65+c4+1] = vv.y; Vs[r*65+c4+2] = vv.z; Vs[r*65+c4+3] = vv.w;
        }
    }
    __syncthreads();

    const int warp = t >> 5, lane = t & 31;
    float* pw = Pb + warp * 72;

    for (int iq = warp * 8; iq < warp * 8 + 8; iq++) {
        const int i = q0 + iq;
        const int j0 = max(0, i - WIN);
        const int nk = i - j0 + 1;

        float sc[3];
        float smax = -1e30f;
        int cnt = 0;
        const float* qr = Qs + iq * 65;
        for (int jj = lane; jj < nk; jj += 32) {
            const float* kr = Ks + (j0 + jj - kbase) * 65;
            float s = 0.f;
#pragma unroll
            for (int d = 0; d < 64; d++) s = fmaf(qr[d], kr[d], s);
            s *= 0.125f;
            sc[cnt++] = s;
            smax = fmaxf(smax, s);
        }
#pragma unroll
        for (int o = 16; o; o >>= 1) smax = fmaxf(smax, __shfl_xor_sync(0xffffffffu, smax, o));

        float ssum = 0.f;
        cnt = 0;
        for (int jj = lane; jj < nk; jj += 32) {
            float e = expf(sc[cnt++] - smax);
            pw[jj] = e;
            ssum += e;
        }
#pragma unroll
        for (int o = 16; o; o >>= 1) ssum += __shfl_xor_sync(0xffffffffu, ssum, o);
        __syncwarp();

        float o0 = 0.f, o1 = 0.f;
        for (int jj = 0; jj < nk; jj++) {
            float p = pw[jj];
            const float* vr = Vs + (j0 + jj - kbase) * 65;
            o0 = fmaf(p, vr[lane], o0);
            o1 = fmaf(p, vr[lane + 32], o1);
        }
        float inv = 1.0f / ssum;
        float* dst = out + ((size_t)(b*SEQ + i)) * DM + h*HD;
        dst[lane]      = o0 * inv;
        dst[lane + 32] = o1 * inv;
        __syncwarp();
    }
}

// ---------------- global attention vs 32 anchors ----------------
__global__ __launch_bounds__(256)
void global_attn_kernel(const float* __restrict__ q, const float* __restrict__ kv,
                        float* __restrict__ out)
{
    __shared__ float Qs[64 * 65];
    __shared__ float Ks[32 * 65];
    __shared__ float Vs[32 * 65];
    __shared__ float Pb[8][36];

    const int qt = blockIdx.x, h = blockIdx.y, b = blockIdx.z;
    const int t = threadIdx.x;
    const int q0 = qt * 64;

    for (int idx = t; idx < 64 * 16; idx += 256) {
        int r = idx >> 4, c4 = (idx & 15) << 2;
        float4 v = *(const float4*)(q + ((size_t)(b*SEQ + q0 + r)) * DM + h*HD + c4);
        Qs[r*65+c4] = v.x; Qs[r*65+c4+1] = v.y; Qs[r*65+c4+2] = v.z; Qs[r*65+c4+3] = v.w;
    }
    for (int idx = t; idx < 32 * 16; idx += 256) {
        int r = idx >> 4, c4 = (idx & 15) << 2;
        const float* base = kv + ((size_t)(b*NA + r)) * (2*DM) + h*HD + c4;
        float4 kk = *(const float4*)base;
        float4 vv = *(const float4*)(base + DM);
        Ks[r*65+c4] = kk.x; Ks[r*65+c4+1] = kk.y; Ks[r*65+c4+2] = kk.z; Ks[r*65+c4+3] = kk.w;
        Vs[r*65+c4] = vv.x; Vs[r*65+c4+1] = vv.y; Vs[r*65+c4+2] = vv.z; Vs[r*65+c4+3] = vv.w;
    }
    __syncthreads();

    const int warp = t >> 5, lane = t & 31;
    for (int iq = warp * 8; iq < warp * 8 + 8; iq++) {
        const float* qr = Qs + iq * 65;
        const float* kr = Ks + lane * 65;
        float s = 0.f;
#pragma unroll
        for (int d = 0; d < 64; d++) s = fmaf(qr[d], kr[d], s);
        s *= 0.125f;
        float smax = s;
#pragma unroll
        for (int o = 16; o; o >>= 1) smax = fmaxf(smax, __shfl_xor_sync(0xffffffffu, smax, o));
        float e = expf(s - smax);
        float ssum = e;
#pragma unroll
        for (int o = 16; o; o >>= 1) ssum += __shfl_xor_sync(0xffffffffu, ssum, o);
        Pb[warp][lane] = e;
        __syncwarp();

        float o0 = 0.f, o1 = 0.f;
#pragma unroll
        for (int j = 0; j < 32; j++) {
            float p = Pb[warp][j];
            o0 = fmaf(p, Vs[j*65 + lane], o0);
            o1 = fmaf(p, Vs[j*65 + lane + 32], o1);
        }
        float inv = 1.0f / ssum;
        float* dst = out + ((size_t)(b*SEQ + q0 + iq)) * DM + h*HD;
        dst[lane]      = o0 * inv;
        dst[lane + 32] = o1 * inv;
        __syncwarp();
    }
}

// ---------------- layernorm ----------------
__global__ __launch_bounds__(128)
void ln_kernel(const float* __restrict__ x, const float* __restrict__ g,
               const float* __restrict__ be, float* __restrict__ out)
{
    __shared__ float red[8];
    const int row = blockIdx.x;
    const int t = threadIdx.x;
    float4 v = ((const float4*)(x + (size_t)row * DM))[t];
    float s  = v.x + v.y + v.z + v.w;
    float ss = v.x*v.x + v.y*v.y + v.z*v.z + v.w*v.w;
#pragma unroll
    for (int o = 16; o; o >>= 1) {
        s  += __shfl_xor_sync(0xffffffffu, s, o);
        ss += __shfl_xor_sync(0xffffffffu, ss, o);
    }
    const int warp = t >> 5, lane = t & 31;
    if (lane == 0) { red[warp] = s; red[warp + 4] = ss; }
    __syncthreads();
    if (t == 0) {
        red[0] = red[0] + red[1] + red[2] + red[3];
        red[4] = red[4] + red[5] + red[6] + red[7];
    }
    __syncthreads();
    float mu  = red[0] * (1.0f / DM);
    float var = red[4] * (1.0f / DM) - mu * mu;
    float inv = rsqrtf(var + 1e-5f);
    float4 gg = ((const float4*)g)[t];
    float4 bb = ((const float4*)be)[t];
    float4 o;
    o.x = (v.x - mu) * inv * gg.x + bb.x;
    o.y = (v.y - mu) * inv * gg.y + bb.y;
    o.z = (v.z - mu) * inv * gg.z + bb.z;
    o.w = (v.w - mu) * inv * gg.w + bb.w;
    ((float4*)(out + (size_t)row * DM))[t] = o;
}

// ---------------- launch ----------------
extern "C" void kernel_launch(void* const* d_in, const int* in_sizes, int n_in,
                              void* d_out, int out_size)
{
    const float* x      = (const float*)d_in[0];
    const float* anchors= (const float*)d_in[1];
    const float* lw_in  = (const float*)d_in[2];
    const float* lb_in  = (const float*)d_in[3];
    const float* lw_out = (const float*)d_in[4];
    const float* lb_out = (const float*)d_in[5];
    const float* gw_in  = (const float*)d_in[6];
    const float* gb_in  = (const float*)d_in[7];
    const float* gw_out = (const float*)d_in[8];
    const float* gb_out = (const float*)d_in[9];
    const float* w1     = (const float*)d_in[10];
    const float* b1     = (const float*)d_in[11];
    const float* w2     = (const float*)d_in[12];
    const float* b2     = (const float*)d_in[13];
    const float* g1     = (const float*)d_in[14];
    const float* be1    = (const float*)d_in[15];
    const float* g2     = (const float*)d_in[16];
    const float* be2    = (const float*)d_in[17];
    float* out = (float*)d_out;

    float *qkv, *attn, *x1, *q2, *kv2, *x2, *x3, *hbuf, *wtf;
    cudaGetSymbolAddress((void**)&qkv,  g_qkv);
    cudaGetSymbolAddress((void**)&attn, g_attn);
    cudaGetSymbolAddress((void**)&x1,   g_x1);
    cudaGetSymbolAddress((void**)&q2,   g_q2);
    cudaGetSymbolAddress((void**)&kv2,  g_kv2);
    cudaGetSymbolAddress((void**)&x2,   g_x2);
    cudaGetSymbolAddress((void**)&x3,   g_x3);
    cudaGetSymbolAddress((void**)&hbuf, g_h);
    cudaGetSymbolAddress((void**)&wtf,  g_wtf);

    const int smem_local = (64*65 + 128*65 + 128*65 + 8*72) * (int)sizeof(float);
    const int gemm_smem  = GEMM_SMEM_F * (int)sizeof(float);
    cudaFuncSetAttribute(local_attn_kernel, cudaFuncAttributeMaxDynamicSharedMemorySize, smem_local);
    cudaFuncSetAttribute(gemm_mma<false>, cudaFuncAttributeMaxDynamicSharedMemorySize, gemm_smem);
    cudaFuncSetAttribute(gemm_mma<true>,  cudaFuncAttributeMaxDynamicSharedMemorySize, gemm_smem);

    dim3 thr(256);

    // [0] pre-round + k-permute all weights (ONE launch)
    cvt_all<<<(WTF_TOTAL + 255) / 256, 256>>>(lw_in, lw_out, gw_in, gw_out, w1, w2, wtf);
    // [1] anchor k,v projection (independent; hoisted so ncu -s 5 lands on gemm_q2)
    gemm_mma<false><<<dim3(1024/256, MAROWS/128), thr, gemm_smem>>>(
        anchors, wtf + OFF_GWIN + 512*512, gb_in + 512, nullptr, kv2, MAROWS, 2*DM, DM);
    // [2] local QKV projection: [32768,1536]
    gemm_mma<false><<<dim3(1536/256, MROWS/128), thr, gemm_smem>>>(
        x, wtf + OFF_LWIN, lb_in, nullptr, qkv, MROWS, 3*DM, DM);
    // [3] windowed causal attention
    local_attn_kernel<<<dim3(SEQ/64, NH, BATCH), thr, smem_local>>>(qkv, attn);
    // [4] local out-proj + residual(x) -> x1
    gemm_mma<false><<<dim3(DM/256, MROWS/128), thr, gemm_smem>>>(
        attn, wtf + OFF_LWOUT, lb_out, x, x1, MROWS, DM, DM);
    // [5] global q projection of x1   <-- ncu capture target
    gemm_mma<false><<<dim3(DM/256, MROWS/128), thr, gemm_smem>>>(
        x1, wtf + OFF_GWIN, gb_in, nullptr, q2, MROWS, DM, DM);
    // [6] global attention (32 keys)
    global_attn_kernel<<<dim3(SEQ/64, NH, BATCH), thr>>>(q2, kv2, attn);
    // [7] global out-proj + residual(x1) -> x2
    gemm_mma<false><<<dim3(DM/256, MROWS/128), thr, gemm_smem>>>(
        attn, wtf + OFF_GWOUT, gb_out, x1, x2, MROWS, DM, DM);
    // [8] LN1 -> x3
    ln_kernel<<<MROWS, 128>>>(x2, g1, be1, x3);
    // [9] FFN1 + exact GELU: [32768,2048]
    gemm_mma<true><<<dim3(FF/256, MROWS/128), thr, gemm_smem>>>(
        x3, wtf + OFF_W1, b1, nullptr, hbuf, MROWS, FF, DM);
    // [10] FFN2 + residual(x3) -> x2
    gemm_mma<false><<<dim3(DM/256, MROWS/128), thr, gemm_smem>>>(
        hbuf, wtf + OFF_W2, b2, x3, x2, MROWS, DM, FF);
    // [11] LN2 -> out
    ln_kernel<<<MROWS, 128>>>(x2, g2, be2, out);
}

// round 6
// speedup vs baseline: 1.6217x; 1.6217x over previous
#include <cuda_runtime.h>
#include <cuda_fp16.h>
#include <math.h>
#include <stdint.h>

#define BATCH 64
#define SEQ   512
#define DM    512
#define NH    8
#define HD    64
#define WIN   64
#define NA    32
#define FF    2048
#define MROWS (BATCH*SEQ)     // 32768
#define MAROWS (BATCH*NA)     // 2048

// ---------------- scratch ----------------
__device__ float g_qkv[(size_t)MROWS * 3 * DM];
__device__ float g_attn[(size_t)MROWS * DM];
__device__ float g_x1 [(size_t)MROWS * DM];
__device__ float g_q2 [(size_t)MROWS * DM];
__device__ float g_kv2[(size_t)MAROWS * 2 * DM];
__device__ float g_x2 [(size_t)MROWS * DM];
__device__ float g_x3 [(size_t)MROWS * DM];
__device__ float g_h  [(size_t)MROWS * FF];
// fp16 weights, packed
#define SZ_LWIN  786432
#define SZ_LWOUT 262144
#define SZ_GWIN  786432
#define SZ_GWOUT 262144
#define SZ_W1    1048576
#define SZ_W2    1048576
#define OFF_LWIN  0
#define OFF_LWOUT (OFF_LWIN + SZ_LWIN)
#define OFF_GWIN  (OFF_LWOUT + SZ_LWOUT)
#define OFF_GWOUT (OFF_GWIN + SZ_GWIN)
#define OFF_W1    (OFF_GWOUT + SZ_GWOUT)
#define OFF_W2    (OFF_W1 + SZ_W1)
#define WTF_TOTAL (OFF_W2 + SZ_W2)
__device__ __half g_wth[(size_t)WTF_TOTAL];

// ================= helpers =================
__device__ __forceinline__ uint32_t smem_u32(const void* p) {
    uint32_t a;
    asm("{ .reg .u64 t; cvta.to.shared.u64 t, %1; cvt.u32.u64 %0, t; }" : "=r"(a) : "l"(p));
    return a;
}
__device__ __forceinline__ uint32_t h2pack(float lo, float hi) {
    __half2 h = __floats2half2_rn(lo, hi);
    return *reinterpret_cast<uint32_t*>(&h);
}
__device__ __forceinline__ void mma16(float* c, const uint32_t* a, const uint32_t* b) {
    asm volatile(
        "mma.sync.aligned.m16n8k16.row.col.f32.f16.f16.f32 "
        "{%0,%1,%2,%3}, {%4,%5,%6,%7}, {%8,%9}, {%0,%1,%2,%3};"
        : "+f"(c[0]), "+f"(c[1]), "+f"(c[2]), "+f"(c[3])
        : "r"(a[0]), "r"(a[1]), "r"(a[2]), "r"(a[3]),
          "r"(b[0]), "r"(b[1]));
}
#define CP_ASYNC16(dst, src) \
    asm volatile("cp.async.cg.shared.global [%0], [%1], 16;" :: "r"(dst), "l"(src) : "memory")
#define CP_COMMIT() asm volatile("cp.async.commit_group;" ::: "memory")
#define CP_WAIT0()  asm volatile("cp.async.wait_group 0;" ::: "memory")

// ---------------- weight fp16 pre-convert (single launch) --------
__global__ __launch_bounds__(256)
void cvt_all(const float* __restrict__ lw_in, const float* __restrict__ lw_out,
             const float* __restrict__ gw_in, const float* __restrict__ gw_out,
             const float* __restrict__ w1, const float* __restrict__ w2,
             __half* __restrict__ dst)
{
    int i = blockIdx.x * 256 + threadIdx.x;
    if (i >= WTF_TOTAL) return;
    const float* src;
    int local;
    if      (i < OFF_LWOUT) { src = lw_in;  local = i - OFF_LWIN; }
    else if (i < OFF_GWIN)  { src = lw_out; local = i - OFF_LWOUT; }
    else if (i < OFF_GWOUT) { src = gw_in;  local = i - OFF_GWIN; }
    else if (i < OFF_W1)    { src = gw_out; local = i - OFF_GWOUT; }
    else if (i < OFF_W2)    { src = w1;     local = i - OFF_W1; }
    else                    { src = w2;     local = i - OFF_W2; }
    dst[i] = __float2half_rn(src[local]);
}

// ================= fp16 m16n8k16 GEMM =================
// C[M,N] = A[M,K] @ W[N,K]^T (+bias)(+res)(gelu)
// CTA 128(M) x 256(N), BK=64 halves (128 B/row), 256 threads, warp tile 64x64.
// Smem in uint32 (half2) words, row stride 36 words (same verified R3 pattern).
#define ROWW 36
#define A_TILE_W (128 * ROWW)   // 4608 words
#define B_TILE_W (256 * ROWW)   // 9216 words
#define GEMM_SMEM_W (2 * (A_TILE_W + B_TILE_W))   // 27648 words = 110592 B

template<bool GELU>
__global__ __launch_bounds__(256, 1)
void gemm_h(const float* __restrict__ A, const __half* __restrict__ W,
            const float* __restrict__ bias, const float* __restrict__ res,
            float* __restrict__ C, int M, int N, int K)
{
    extern __shared__ uint32_t smh[];
    uint32_t* As[2] = { smh, smh + A_TILE_W };
    uint32_t* Bs[2] = { smh + 2 * A_TILE_W, smh + 2 * A_TILE_W + B_TILE_W };

    const int t = threadIdx.x;
    const int wid = t >> 5, lane = t & 31;
    const int gid = lane >> 2, tig = lane & 3;
    const int wm = wid >> 2;            // 0..1
    const int wn = wid & 3;             // 0..3
    const int bm = blockIdx.y * 128;
    const int bn = blockIdx.x * 256;

    const int ar = t >> 3;              // 0..31
    const int ach = (t & 7) << 3;       // half/float chunk: 8 elems

    const float*  Abase = A + (size_t)(bm + ar) * K + ach;
    const __half* Wbase = W + (size_t)(bn + ar) * K + ach;
    // B smem dst word offset for this thread (per row-block):
    const uint32_t boff = (uint32_t)(ar * ROWW + (t & 7) * 4) * 4u;
    // A smem dst
    const int aoffw = ar * ROWW + (t & 7) * 4;

    float acc[4][8][4];
#pragma unroll
    for (int i = 0; i < 4; i++)
#pragma unroll
        for (int j = 0; j < 8; j++)
#pragma unroll
            for (int q = 0; q < 4; q++) acc[i][j][q] = 0.f;

    const int KT = K >> 6;              // 64 k per tile

    // ---- prologue: tile 0 ----
    {
        float4 av0[4], av1[4];
#pragma unroll
        for (int i = 0; i < 4; i++) {
            av0[i] = *(const float4*)(Abase + (size_t)(i * 32) * K);
            av1[i] = *(const float4*)(Abase + (size_t)(i * 32) * K + 4);
        }
        uint32_t bdst = smem_u32(Bs[0]) + boff;
#pragma unroll
        for (int i = 0; i < 8; i++)
            CP_ASYNC16(bdst + (uint32_t)(i * 32 * ROWW * 4), Wbase + (size_t)(i * 32) * K);
        CP_COMMIT();
#pragma unroll
        for (int i = 0; i < 4; i++) {
            uint32_t* d = As[0] + aoffw + i * 32 * ROWW;
            d[0] = h2pack(av0[i].x, av0[i].y);
            d[1] = h2pack(av0[i].z, av0[i].w);
            d[2] = h2pack(av1[i].x, av1[i].y);
            d[3] = h2pack(av1[i].z, av1[i].w);
        }
        CP_WAIT0();
        __syncthreads();
    }

    for (int kt = 0; kt < KT; kt++) {
        const int buf = kt & 1;
        const bool more = (kt + 1) < KT;
        float4 av0[4], av1[4];
        if (more) {
            const float*  Ap = Abase + (size_t)(kt + 1) * 64;
            const __half* Wp = Wbase + (size_t)(kt + 1) * 64;
#pragma unroll
            for (int i = 0; i < 4; i++) {
                av0[i] = *(const float4*)(Ap + (size_t)(i * 32) * K);
                av1[i] = *(const float4*)(Ap + (size_t)(i * 32) * K + 4);
            }
            uint32_t bdst = smem_u32(Bs[buf ^ 1]) + boff;
#pragma unroll
            for (int i = 0; i < 8; i++)
                CP_ASYNC16(bdst + (uint32_t)(i * 32 * ROWW * 4), Wp + (size_t)(i * 32) * K);
            CP_COMMIT();
        }

        const uint32_t* Ab = As[buf];
        const uint32_t* Bb = Bs[buf];
#pragma unroll
        for (int kk = 0; kk < 4; kk++) {
            uint32_t a[4][4], b[8][2];
#pragma unroll
            for (int i = 0; i < 4; i++) {
                int m = wm * 64 + i * 16 + gid;
                a[i][0] = Ab[m * ROWW + kk * 8 + tig];
                a[i][1] = Ab[(m + 8) * ROWW + kk * 8 + tig];
                a[i][2] = Ab[m * ROWW + kk * 8 + tig + 4];
                a[i][3] = Ab[(m + 8) * ROWW + kk * 8 + tig + 4];
            }
#pragma unroll
            for (int j = 0; j < 8; j++) {
                int n = wn * 64 + j * 8 + gid;
                b[j][0] = Bb[n * ROWW + kk * 8 + tig];
                b[j][1] = Bb[n * ROWW + kk * 8 + tig + 4];
            }
#pragma unroll
            for (int i = 0; i < 4; i++)
#pragma unroll
                for (int j = 0; j < 8; j++)
                    mma16(acc[i][j], a[i], b[j]);
        }

        if (more) {
#pragma unroll
            for (int i = 0; i < 4; i++) {
                uint32_t* d = As[buf ^ 1] + aoffw + i * 32 * ROWW;
                d[0] = h2pack(av0[i].x, av0[i].y);
                d[1] = h2pack(av0[i].z, av0[i].w);
                d[2] = h2pack(av1[i].x, av1[i].y);
                d[3] = h2pack(av1[i].z, av1[i].w);
            }
            CP_WAIT0();
        }
        __syncthreads();
    }

    // ---- epilogue ----
#pragma unroll
    for (int j = 0; j < 8; j++) {
        const int gc = bn + wn * 64 + j * 8 + 2 * tig;
        const float2 bia = *(const float2*)(bias + gc);
#pragma unroll
        for (int i = 0; i < 4; i++) {
            const int gr = bm + wm * 64 + i * 16 + gid;
            float2 v0, v1;
            v0.x = acc[i][j][0] + bia.x; v0.y = acc[i][j][1] + bia.y;
            v1.x = acc[i][j][2] + bia.x; v1.y = acc[i][j][3] + bia.y;
            if (res) {
                float2 r0 = *(const float2*)(res + (size_t)gr * N + gc);
                float2 r1 = *(const float2*)(res + (size_t)(gr + 8) * N + gc);
                v0.x += r0.x; v0.y += r0.y; v1.x += r1.x; v1.y += r1.y;
            }
            if (GELU) {
                v0.x = 0.5f * v0.x * (1.0f + erff(v0.x * 0.70710678118654752f));
                v0.y = 0.5f * v0.y * (1.0f + erff(v0.y * 0.70710678118654752f));
                v1.x = 0.5f * v1.x * (1.0f + erff(v1.x * 0.70710678118654752f));
                v1.y = 0.5f * v1.y * (1.0f + erff(v1.y * 0.70710678118654752f));
            }
            *(float2*)(C + (size_t)gr * N + gc) = v0;
            *(float2*)(C + (size_t)(gr + 8) * N + gc) = v1;
        }
    }
}

// ---------------- local windowed causal attention (proven SIMT version) ------
__global__ __launch_bounds__(256)
void local_attn_kernel(const float* __restrict__ qkv, float* __restrict__ out)
{
    extern __shared__ float sml[];
    float* Qs = sml;
    float* Ks = Qs + 64 * 65;
    float* Vs = Ks + 128 * 65;
    float* Pb = Vs + 128 * 65;

    const int qt = blockIdx.x, h = blockIdx.y, b = blockIdx.z;
    const int t = threadIdx.x;
    const int q0 = qt * 64;
    const int kbase = q0 - 64;

    for (int idx = t; idx < 64 * 16; idx += 256) {
        int r = idx >> 4, c4 = (idx & 15) << 2;
        float4 v = *(const float4*)(qkv + ((size_t)(b*SEQ + q0 + r)) * (3*DM) + h*HD + c4);
        Qs[r*65+c4] = v.x; Qs[r*65+c4+1] = v.y; Qs[r*65+c4+2] = v.z; Qs[r*65+c4+3] = v.w;
    }
    for (int idx = t; idx < 128 * 16; idx += 256) {
        int r = idx >> 4, c4 = (idx & 15) << 2;
        int j = kbase + r;
        if (j >= 0) {
            const float* base = qkv + ((size_t)(b*SEQ + j)) * (3*DM) + DM + h*HD + c4;
            float4 kv = *(const float4*)base;
            float4 vv = *(const float4*)(base + DM);
            Ks[r*65+c4] = kv.x; Ks[r*65+c4+1] = kv.y; Ks[r*65+c4+2] = kv.z; Ks[r*65+c4+3] = kv.w;
            Vs[r*65+c4] = vv.x; Vs[r*65+c4+1] = vv.y; Vs[r*65+c4+2] = vv.z; Vs[r*65+c4+3] = vv.w;
        }
    }
    __syncthreads();

    const int warp = t >> 5, lane = t & 31;
    float* pw = Pb + warp * 72;

    for (int iq = warp * 8; iq < warp * 8 + 8; iq++) {
        const int i = q0 + iq;
        const int j0 = max(0, i - WIN);
        const int nk = i - j0 + 1;

        float sc[3];
        float smax = -1e30f;
        int cnt = 0;
        const float* qr = Qs + iq * 65;
        for (int jj = lane; jj < nk; jj += 32) {
            const float* kr = Ks + (j0 + jj - kbase) * 65;
            float s = 0.f;
#pragma unroll
            for (int d = 0; d < 64; d++) s = fmaf(qr[d], kr[d], s);
            s *= 0.125f;
            sc[cnt++] = s;
            smax = fmaxf(smax, s);
        }
#pragma unroll
        for (int o = 16; o; o >>= 1) smax = fmaxf(smax, __shfl_xor_sync(0xffffffffu, smax, o));

        float ssum = 0.f;
        cnt = 0;
        for (int jj = lane; jj < nk; jj += 32) {
            float e = expf(sc[cnt++] - smax);
            pw[jj] = e;
            ssum += e;
        }
#pragma unroll
        for (int o = 16; o; o >>= 1) ssum += __shfl_xor_sync(0xffffffffu, ssum, o);
        __syncwarp();

        float o0 = 0.f, o1 = 0.f;
        for (int jj = 0; jj < nk; jj++) {
            float p = pw[jj];
            const float* vr = Vs + (j0 + jj - kbase) * 65;
            o0 = fmaf(p, vr[lane], o0);
            o1 = fmaf(p, vr[lane + 32], o1);
        }
        float inv = 1.0f / ssum;
        float* dst = out + ((size_t)(b*SEQ + i)) * DM + h*HD;
        dst[lane]      = o0 * inv;
        dst[lane + 32] = o1 * inv;
        __syncwarp();
    }
}

// ---------------- global attention vs 32 anchors ----------------
__global__ __launch_bounds__(256)
void global_attn_kernel(const float* __restrict__ q, const float* __restrict__ kv,
                        float* __restrict__ out)
{
    __shared__ float Qs[64 * 65];
    __shared__ float Ks[32 * 65];
    __shared__ float Vs[32 * 65];
    __shared__ float Pb[8][36];

    const int qt = blockIdx.x, h = blockIdx.y, b = blockIdx.z;
    const int t = threadIdx.x;
    const int q0 = qt * 64;

    for (int idx = t; idx < 64 * 16; idx += 256) {
        int r = idx >> 4, c4 = (idx & 15) << 2;
        float4 v = *(const float4*)(q + ((size_t)(b*SEQ + q0 + r)) * DM + h*HD + c4);
        Qs[r*65+c4] = v.x; Qs[r*65+c4+1] = v.y; Qs[r*65+c4+2] = v.z; Qs[r*65+c4+3] = v.w;
    }
    for (int idx = t; idx < 32 * 16; idx += 256) {
        int r = idx >> 4, c4 = (idx & 15) << 2;
        const float* base = kv + ((size_t)(b*NA + r)) * (2*DM) + h*HD + c4;
        float4 kk = *(const float4*)base;
        float4 vv = *(const float4*)(base + DM);
        Ks[r*65+c4] = kk.x; Ks[r*65+c4+1] = kk.y; Ks[r*65+c4+2] = kk.z; Ks[r*65+c4+3] = kk.w;
        Vs[r*65+c4] = vv.x; Vs[r*65+c4+1] = vv.y; Vs[r*65+c4+2] = vv.z; Vs[r*65+c4+3] = vv.w;
    }
    __syncthreads();

    const int warp = t >> 5, lane = t & 31;
    for (int iq = warp * 8; iq < warp * 8 + 8; iq++) {
        const float* qr = Qs + iq * 65;
        const float* kr = Ks + lane * 65;
        float s = 0.f;
#pragma unroll
        for (int d = 0; d < 64; d++) s = fmaf(qr[d], kr[d], s);
        s *= 0.125f;
        float smax = s;
#pragma unroll
        for (int o = 16; o; o >>= 1) smax = fmaxf(smax, __shfl_xor_sync(0xffffffffu, smax, o));
        float e = expf(s - smax);
        float ssum = e;
#pragma unroll
        for (int o = 16; o; o >>= 1) ssum += __shfl_xor_sync(0xffffffffu, ssum, o);
        Pb[warp][lane] = e;
        __syncwarp();

        float o0 = 0.f, o1 = 0.f;
#pragma unroll
        for (int j = 0; j < 32; j++) {
            float p = Pb[warp][j];
            o0 = fmaf(p, Vs[j*65 + lane], o0);
            o1 = fmaf(p, Vs[j*65 + lane + 32], o1);
        }
        float inv = 1.0f / ssum;
        float* dst = out + ((size_t)(b*SEQ + q0 + iq)) * DM + h*HD;
        dst[lane]      = o0 * inv;
        dst[lane + 32] = o1 * inv;
        __syncwarp();
    }
}

// ---------------- layernorm ----------------
__global__ __launch_bounds__(128)
void ln_kernel(const float* __restrict__ x, const float* __restrict__ g,
               const float* __restrict__ be, float* __restrict__ out)
{
    __shared__ float red[8];
    const int row = blockIdx.x;
    const int t = threadIdx.x;
    float4 v = ((const float4*)(x + (size_t)row * DM))[t];
    float s  = v.x + v.y + v.z + v.w;
    float ss = v.x*v.x + v.y*v.y + v.z*v.z + v.w*v.w;
#pragma unroll
    for (int o = 16; o; o >>= 1) {
        s  += __shfl_xor_sync(0xffffffffu, s, o);
        ss += __shfl_xor_sync(0xffffffffu, ss, o);
    }
    const int warp = t >> 5, lane = t & 31;
    if (lane == 0) { red[warp] = s; red[warp + 4] = ss; }
    __syncthreads();
    if (t == 0) {
        red[0] = red[0] + red[1] + red[2] + red[3];
        red[4] = red[4] + red[5] + red[6] + red[7];
    }
    __syncthreads();
    float mu  = red[0] * (1.0f / DM);
    float var = red[4] * (1.0f / DM) - mu * mu;
    float inv = rsqrtf(var + 1e-5f);
    float4 gg = ((const float4*)g)[t];
    float4 bb = ((const float4*)be)[t];
    float4 o;
    o.x = (v.x - mu) * inv * gg.x + bb.x;
    o.y = (v.y - mu) * inv * gg.y + bb.y;
    o.z = (v.z - mu) * inv * gg.z + bb.z;
    o.w = (v.w - mu) * inv * gg.w + bb.w;
    ((float4*)(out + (size_t)row * DM))[t] = o;
}

// ---------------- launch ----------------
extern "C" void kernel_launch(void* const* d_in, const int* in_sizes, int n_in,
                              void* d_out, int out_size)
{
    const float* x      = (const float*)d_in[0];
    const float* anchors= (const float*)d_in[1];
    const float* lw_in  = (const float*)d_in[2];
    const float* lb_in  = (const float*)d_in[3];
    const float* lw_out = (const float*)d_in[4];
    const float* lb_out = (const float*)d_in[5];
    const float* gw_in  = (const float*)d_in[6];
    const float* gb_in  = (const float*)d_in[7];
    const float* gw_out = (const float*)d_in[8];
    const float* gb_out = (const float*)d_in[9];
    const float* w1     = (const float*)d_in[10];
    const float* b1     = (const float*)d_in[11];
    const float* w2     = (const float*)d_in[12];
    const float* b2     = (const float*)d_in[13];
    const float* g1     = (const float*)d_in[14];
    const float* be1    = (const float*)d_in[15];
    const float* g2     = (const float*)d_in[16];
    const float* be2    = (const float*)d_in[17];
    float* out = (float*)d_out;

    float *qkv, *attn, *x1, *q2, *kv2, *x2, *x3, *hbuf;
    __half* wth;
    cudaGetSymbolAddress((void**)&qkv,  g_qkv);
    cudaGetSymbolAddress((void**)&attn, g_attn);
    cudaGetSymbolAddress((void**)&x1,   g_x1);
    cudaGetSymbolAddress((void**)&q2,   g_q2);
    cudaGetSymbolAddress((void**)&kv2,  g_kv2);
    cudaGetSymbolAddress((void**)&x2,   g_x2);
    cudaGetSymbolAddress((void**)&x3,   g_x3);
    cudaGetSymbolAddress((void**)&hbuf, g_h);
    cudaGetSymbolAddress((void**)&wth,  g_wth);

    const int smem_local = (64*65 + 128*65 + 128*65 + 8*72) * (int)sizeof(float);
    const int gemm_smem  = GEMM_SMEM_W * (int)sizeof(uint32_t);
    cudaFuncSetAttribute(local_attn_kernel, cudaFuncAttributeMaxDynamicSharedMemorySize, smem_local);
    cudaFuncSetAttribute(gemm_h<false>, cudaFuncAttributeMaxDynamicSharedMemorySize, gemm_smem);
    cudaFuncSetAttribute(gemm_h<true>,  cudaFuncAttributeMaxDynamicSharedMemorySize, gemm_smem);

    dim3 thr(256);

    // [0] weight fp16 pre-round (one launch)
    cvt_all<<<(WTF_TOTAL + 255) / 256, 256>>>(lw_in, lw_out, gw_in, gw_out, w1, w2, wth);
    // [1] anchor k,v projection
    gemm_h<false><<<dim3(1024/256, MAROWS/128), thr, gemm_smem>>>(
        anchors, wth + OFF_GWIN + 512*512, gb_in + 512, nullptr, kv2, MAROWS, 2*DM, DM);
    // [2] local QKV projection
    gemm_h<false><<<dim3(1536/256, MROWS/128), thr, gemm_smem>>>(
        x, wth + OFF_LWIN, lb_in, nullptr, qkv, MROWS, 3*DM, DM);
    // [3] windowed causal attention (SIMT, proven)
    local_attn_kernel<<<dim3(SEQ/64, NH, BATCH), thr, smem_local>>>(qkv, attn);
    // [4] local out-proj + residual(x) -> x1
    gemm_h<false><<<dim3(DM/256, MROWS/128), thr, gemm_smem>>>(
        attn, wth + OFF_LWOUT, lb_out, x, x1, MROWS, DM, DM);
    // [5] global q projection of x1   <-- ncu capture target (launch #6)
    gemm_h<false><<<dim3(DM/256, MROWS/128), thr, gemm_smem>>>(
        x1, wth + OFF_GWIN, gb_in, nullptr, q2, MROWS, DM, DM);
    // [6] global attention (32 keys)
    global_attn_kernel<<<dim3(SEQ/64, NH, BATCH), thr>>>(q2, kv2, attn);
    // [7] global out-proj + residual(x1) -> x2
    gemm_h<false><<<dim3(DM/256, MROWS/128), thr, gemm_smem>>>(
        attn, wth + OFF_GWOUT, gb_out, x1, x2, MROWS, DM, DM);
    // [8] LN1 -> x3
    ln_kernel<<<MROWS, 128>>>(x2, g1, be1, x3);
    // [9] FFN1 + exact GELU
    gemm_h<true><<<dim3(FF/256, MROWS/128), thr, gemm_smem>>>(
        x3, wth + OFF_W1, b1, nullptr, hbuf, MROWS, FF, DM);
    // [10] FFN2 + residual(x3) -> x2
    gemm_h<false><<<dim3(DM/256, MROWS/128), thr, gemm_smem>>>(
        hbuf, wth + OFF_W2, b2, x3, x2, MROWS, DM, FF);
    // [11] LN2 -> out
    ln_kernel<<<MROWS, 128>>>(x2, g2, be2, out);
}

// round 7
// speedup vs baseline: 1.6514x; 1.0183x over previous
#include <cuda_runtime.h>
#include <cuda_fp16.h>
#include <math.h>
#include <stdint.h>

#define BATCH 64
#define SEQ   512
#define DM    512
#define NH    8
#define HD    64
#define WIN   64
#define NA    32
#define FF    2048
#define MROWS (BATCH*SEQ)     // 32768
#define MAROWS (BATCH*NA)     // 2048

// ---------------- scratch ----------------
__device__ float g_qkv[(size_t)MROWS * 3 * DM];
__device__ float g_attn[(size_t)MROWS * DM];
__device__ float g_x1 [(size_t)MROWS * DM];
__device__ float g_q2 [(size_t)MROWS * DM];
__device__ float g_kv2[(size_t)MAROWS * 2 * DM];
__device__ float g_x2 [(size_t)MROWS * DM];
__device__ float g_x3 [(size_t)MROWS * DM];
__device__ float g_h  [(size_t)MROWS * FF];
// fp16 weights, packed
#define SZ_LWIN  786432
#define SZ_LWOUT 262144
#define SZ_GWIN  786432
#define SZ_GWOUT 262144
#define SZ_W1    1048576
#define SZ_W2    1048576
#define OFF_LWIN  0
#define OFF_LWOUT (OFF_LWIN + SZ_LWIN)
#define OFF_GWIN  (OFF_LWOUT + SZ_LWOUT)
#define OFF_GWOUT (OFF_GWIN + SZ_GWIN)
#define OFF_W1    (OFF_GWOUT + SZ_GWOUT)
#define OFF_W2    (OFF_W1 + SZ_W1)
#define WTF_TOTAL (OFF_W2 + SZ_W2)
__device__ __half g_wth[(size_t)WTF_TOTAL];

// ================= helpers =================
__device__ __forceinline__ uint32_t smem_u32(const void* p) {
    uint32_t a;
    asm("{ .reg .u64 t; cvta.to.shared.u64 t, %1; cvt.u32.u64 %0, t; }" : "=r"(a) : "l"(p));
    return a;
}
__device__ __forceinline__ uint32_t h2pack(float lo, float hi) {
    __half2 h = __floats2half2_rn(lo, hi);
    return *reinterpret_cast<uint32_t*>(&h);
}
__device__ __forceinline__ void mma16(float* c, const uint32_t* a, const uint32_t* b) {
    asm volatile(
        "mma.sync.aligned.m16n8k16.row.col.f32.f16.f16.f32 "
        "{%0,%1,%2,%3}, {%4,%5,%6,%7}, {%8,%9}, {%0,%1,%2,%3};"
        : "+f"(c[0]), "+f"(c[1]), "+f"(c[2]), "+f"(c[3])
        : "r"(a[0]), "r"(a[1]), "r"(a[2]), "r"(a[3]),
          "r"(b[0]), "r"(b[1]));
}
#define CP_ASYNC16(dst, src) \
    asm volatile("cp.async.cg.shared.global [%0], [%1], 16;" :: "r"(dst), "l"(src) : "memory")
#define CP_COMMIT() asm volatile("cp.async.commit_group;" ::: "memory")
#define CP_WAIT0()  asm volatile("cp.async.wait_group 0;" ::: "memory")

// ---------------- weight fp16 pre-convert (single launch) --------
__global__ __launch_bounds__(256)
void cvt_all(const float* __restrict__ lw_in, const float* __restrict__ lw_out,
             const float* __restrict__ gw_in, const float* __restrict__ gw_out,
             const float* __restrict__ w1, const float* __restrict__ w2,
             __half* __restrict__ dst)
{
    int i = blockIdx.x * 256 + threadIdx.x;
    if (i >= WTF_TOTAL) return;
    const float* src;
    int local;
    if      (i < OFF_LWOUT) { src = lw_in;  local = i - OFF_LWIN; }
    else if (i < OFF_GWIN)  { src = lw_out; local = i - OFF_LWOUT; }
    else if (i < OFF_GWOUT) { src = gw_in;  local = i - OFF_GWIN; }
    else if (i < OFF_W1)    { src = gw_out; local = i - OFF_GWOUT; }
    else if (i < OFF_W2)    { src = w1;     local = i - OFF_W1; }
    else                    { src = w2;     local = i - OFF_W2; }
    dst[i] = __float2half_rn(src[local]);
}

// ================= fp16 m16n8k16 GEMM (unchanged from R6) =================
#define ROWW 36
#define A_TILE_W (128 * ROWW)
#define B_TILE_W (256 * ROWW)
#define GEMM_SMEM_W (2 * (A_TILE_W + B_TILE_W))

template<bool GELU>
__global__ __launch_bounds__(256, 1)
void gemm_h(const float* __restrict__ A, const __half* __restrict__ W,
            const float* __restrict__ bias, const float* __restrict__ res,
            float* __restrict__ C, int M, int N, int K)
{
    extern __shared__ uint32_t smh[];
    uint32_t* As[2] = { smh, smh + A_TILE_W };
    uint32_t* Bs[2] = { smh + 2 * A_TILE_W, smh + 2 * A_TILE_W + B_TILE_W };

    const int t = threadIdx.x;
    const int wid = t >> 5, lane = t & 31;
    const int gid = lane >> 2, tig = lane & 3;
    const int wm = wid >> 2;
    const int wn = wid & 3;
    const int bm = blockIdx.y * 128;
    const int bn = blockIdx.x * 256;

    const int ar = t >> 3;
    const int ach = (t & 7) << 3;

    const float*  Abase = A + (size_t)(bm + ar) * K + ach;
    const __half* Wbase = W + (size_t)(bn + ar) * K + ach;
    const uint32_t boff = (uint32_t)(ar * ROWW + (t & 7) * 4) * 4u;
    const int aoffw = ar * ROWW + (t & 7) * 4;

    float acc[4][8][4];
#pragma unroll
    for (int i = 0; i < 4; i++)
#pragma unroll
        for (int j = 0; j < 8; j++)
#pragma unroll
            for (int q = 0; q < 4; q++) acc[i][j][q] = 0.f;

    const int KT = K >> 6;

    {
        float4 av0[4], av1[4];
#pragma unroll
        for (int i = 0; i < 4; i++) {
            av0[i] = *(const float4*)(Abase + (size_t)(i * 32) * K);
            av1[i] = *(const float4*)(Abase + (size_t)(i * 32) * K + 4);
        }
        uint32_t bdst = smem_u32(Bs[0]) + boff;
#pragma unroll
        for (int i = 0; i < 8; i++)
            CP_ASYNC16(bdst + (uint32_t)(i * 32 * ROWW * 4), Wbase + (size_t)(i * 32) * K);
        CP_COMMIT();
#pragma unroll
        for (int i = 0; i < 4; i++) {
            uint32_t* d = As[0] + aoffw + i * 32 * ROWW;
            d[0] = h2pack(av0[i].x, av0[i].y);
            d[1] = h2pack(av0[i].z, av0[i].w);
            d[2] = h2pack(av1[i].x, av1[i].y);
            d[3] = h2pack(av1[i].z, av1[i].w);
        }
        CP_WAIT0();
        __syncthreads();
    }

    for (int kt = 0; kt < KT; kt++) {
        const int buf = kt & 1;
        const bool more = (kt + 1) < KT;
        float4 av0[4], av1[4];
        if (more) {
            const float*  Ap = Abase + (size_t)(kt + 1) * 64;
            const __half* Wp = Wbase + (size_t)(kt + 1) * 64;
#pragma unroll
            for (int i = 0; i < 4; i++) {
                av0[i] = *(const float4*)(Ap + (size_t)(i * 32) * K);
                av1[i] = *(const float4*)(Ap + (size_t)(i * 32) * K + 4);
            }
            uint32_t bdst = smem_u32(Bs[buf ^ 1]) + boff;
#pragma unroll
            for (int i = 0; i < 8; i++)
                CP_ASYNC16(bdst + (uint32_t)(i * 32 * ROWW * 4), Wp + (size_t)(i * 32) * K);
            CP_COMMIT();
        }

        const uint32_t* Ab = As[buf];
        const uint32_t* Bb = Bs[buf];
#pragma unroll
        for (int kk = 0; kk < 4; kk++) {
            uint32_t a[4][4], b[8][2];
#pragma unroll
            for (int i = 0; i < 4; i++) {
                int m = wm * 64 + i * 16 + gid;
                a[i][0] = Ab[m * ROWW + kk * 8 + tig];
                a[i][1] = Ab[(m + 8) * ROWW + kk * 8 + tig];
                a[i][2] = Ab[m * ROWW + kk * 8 + tig + 4];
                a[i][3] = Ab[(m + 8) * ROWW + kk * 8 + tig + 4];
            }
#pragma unroll
            for (int j = 0; j < 8; j++) {
                int n = wn * 64 + j * 8 + gid;
                b[j][0] = Bb[n * ROWW + kk * 8 + tig];
                b[j][1] = Bb[n * ROWW + kk * 8 + tig + 4];
            }
#pragma unroll
            for (int i = 0; i < 4; i++)
#pragma unroll
                for (int j = 0; j < 8; j++)
                    mma16(acc[i][j], a[i], b[j]);
        }

        if (more) {
#pragma unroll
            for (int i = 0; i < 4; i++) {
                uint32_t* d = As[buf ^ 1] + aoffw + i * 32 * ROWW;
                d[0] = h2pack(av0[i].x, av0[i].y);
                d[1] = h2pack(av0[i].z, av0[i].w);
                d[2] = h2pack(av1[i].x, av1[i].y);
                d[3] = h2pack(av1[i].z, av1[i].w);
            }
            CP_WAIT0();
        }
        __syncthreads();
    }

#pragma unroll
    for (int j = 0; j < 8; j++) {
        const int gc = bn + wn * 64 + j * 8 + 2 * tig;
        const float2 bia = *(const float2*)(bias + gc);
#pragma unroll
        for (int i = 0; i < 4; i++) {
            const int gr = bm + wm * 64 + i * 16 + gid;
            float2 v0, v1;
            v0.x = acc[i][j][0] + bia.x; v0.y = acc[i][j][1] + bia.y;
            v1.x = acc[i][j][2] + bia.x; v1.y = acc[i][j][3] + bia.y;
            if (res) {
                float2 r0 = *(const float2*)(res + (size_t)gr * N + gc);
                float2 r1 = *(const float2*)(res + (size_t)(gr + 8) * N + gc);
                v0.x += r0.x; v0.y += r0.y; v1.x += r1.x; v1.y += r1.y;
            }
            if (GELU) {
                v0.x = 0.5f * v0.x * (1.0f + erff(v0.x * 0.70710678118654752f));
                v0.y = 0.5f * v0.y * (1.0f + erff(v0.y * 0.70710678118654752f));
                v1.x = 0.5f * v1.x * (1.0f + erff(v1.x * 0.70710678118654752f));
                v1.y = 0.5f * v1.y * (1.0f + erff(v1.y * 0.70710678118654752f));
            }
            *(float2*)(C + (size_t)gr * N + gc) = v0;
            *(float2*)(C + (size_t)(gr + 8) * N + gc) = v1;
        }
    }
}

// ================= local windowed causal attention — vectorized LDS.128 ======
// Layouts: Qs[64][68], Ks[128][68] (row=key), Vt[64][132] (dim-major), Pb[8][132].
// Strides 68/132 give 16B-aligned rows and conflict-free float4 access
// (bank(r,d) = (4r+d) mod 32, consecutive lanes -> consecutive rows).
#define LQS 68
#define LVS 132
#define LA_SMEM_F (64*LQS + 128*LQS + 64*LVS + 8*LVS)   // 22560 floats = 90240 B

__global__ __launch_bounds__(256)
void local_attn_kernel(const float* __restrict__ qkv, float* __restrict__ out)
{
    extern __shared__ float sml[];
    float* Qs = sml;                    // [64][LQS]
    float* Ks = Qs + 64 * LQS;          // [128][LQS]
    float* Vt = Ks + 128 * LQS;         // [64][LVS] dim-major
    float* Pb = Vt + 64 * LVS;          // [8][LVS]

    const int qt = blockIdx.x, h = blockIdx.y, b = blockIdx.z;
    const int t = threadIdx.x;
    const int q0 = qt * 64;
    const int kbase = q0 - 64;

    // Q tile (64 rows x 64 dims), float4
    for (int idx = t; idx < 64 * 16; idx += 256) {
        int r = idx >> 4, c4 = (idx & 15) << 2;
        float4 v = *(const float4*)(qkv + ((size_t)(b*SEQ + q0 + r)) * (3*DM) + h*HD + c4);
        *(float4*)(Qs + r * LQS + c4) = v;
    }
    // K tile (128 rows), float4 (rows j<0 never read)
    for (int idx = t; idx < 128 * 16; idx += 256) {
        int r = idx >> 4, c4 = (idx & 15) << 2;
        int j = kbase + r;
        if (j >= 0) {
            float4 kv = *(const float4*)(qkv + ((size_t)(b*SEQ + j)) * (3*DM) + DM + h*HD + c4);
            *(float4*)(Ks + r * LQS + c4) = kv;
        }
    }
    // V transposed (dim-major): lanes span consecutive keys -> conflict-free STS
#pragma unroll
    for (int pass = 0; pass < 8; pass++) {
        int r  = (t & 31) + 32 * (pass & 3);          // key row 0..127
        int c4 = (((t >> 5) + 8 * (pass >> 2))) << 2; // dim 0..60 step 4
        int j = kbase + r;
        if (j >= 0) {
            float4 vv = *(const float4*)(qkv + ((size_t)(b*SEQ + j)) * (3*DM) + 2*DM + h*HD + c4);
            Vt[(c4+0) * LVS + r] = vv.x;
            Vt[(c4+1) * LVS + r] = vv.y;
            Vt[(c4+2) * LVS + r] = vv.z;
            Vt[(c4+3) * LVS + r] = vv.w;
        }
    }
    __syncthreads();

    const int warp = t >> 5, lane = t & 31;
    float* pw = Pb + warp * LVS;

    for (int iq = warp * 8; iq < warp * 8 + 8; iq++) {
        const int i = q0 + iq;
        const int rlo = max(0, i - WIN) - kbase;      // first key row
        const int nk = (i - kbase) - rlo + 1;         // <= 65 keys
        const float4* qr4 = (const float4*)(Qs + iq * LQS);

        float sc[3];
        float smax = -1e30f;
        int cnt = 0;
        for (int jj = lane; jj < nk; jj += 32) {
            const float4* kr4 = (const float4*)(Ks + (rlo + jj) * LQS);
            float s = 0.f;
#pragma unroll
            for (int d = 0; d < 16; d++) {
                float4 q4 = qr4[d], k4 = kr4[d];
                s += q4.x*k4.x + q4.y*k4.y + q4.z*k4.z + q4.w*k4.w;
            }
            s *= 0.125f;
            sc[cnt++] = s;
            smax = fmaxf(smax, s);
        }
#pragma unroll
        for (int o = 16; o; o >>= 1) smax = fmaxf(smax, __shfl_xor_sync(0xffffffffu, smax, o));

        float ssum = 0.f;
        cnt = 0;
        for (int jj = lane; jj < nk; jj += 32) {
            float e = expf(sc[cnt++] - smax);
            pw[rlo + jj] = e;
            ssum += e;
        }
#pragma unroll
        for (int o = 16; o; o >>= 1) ssum += __shfl_xor_sync(0xffffffffu, ssum, o);

        // zero-pad pw to 4-aligned range [lo4, hi4)
        const int lo4 = rlo & ~3;
        const int hi  = rlo + nk;
        const int hi4 = (hi + 3) & ~3;
        if (lane < rlo - lo4) pw[lo4 + lane] = 0.f;
        if (lane < hi4 - hi)  pw[hi + lane] = 0.f;
        __syncwarp();

        // PV: lane owns dims (lane, lane+32); float4 across key rows
        float o0 = 0.f, o1 = 0.f;
        const float* va = Vt + lane * LVS;
        const float* vb = Vt + (lane + 32) * LVS;
        for (int r4 = lo4; r4 < hi4; r4 += 4) {
            float4 p  = *(const float4*)(pw + r4);
            float4 a4 = *(const float4*)(va + r4);
            float4 b4 = *(const float4*)(vb + r4);
            o0 += p.x*a4.x + p.y*a4.y + p.z*a4.z + p.w*a4.w;
            o1 += p.x*b4.x + p.y*b4.y + p.z*b4.z + p.w*b4.w;
        }
        const float inv = 1.0f / ssum;
        float* dst = out + ((size_t)(b*SEQ + i)) * DM + h*HD;
        dst[lane]      = o0 * inv;
        dst[lane + 32] = o1 * inv;
        __syncwarp();
    }
}

// ---------------- global attention vs 32 anchors — vectorized ----------------
#define GQS 68
#define GVS 36
__global__ __launch_bounds__(256)
void global_attn_kernel(const float* __restrict__ q, const float* __restrict__ kv,
                        float* __restrict__ out)
{
    __shared__ __align__(16) float Qs[64 * GQS];
    __shared__ __align__(16) float Ks[32 * GQS];
    __shared__ __align__(16) float Vt[64 * GVS];   // dim-major [64][36]
    __shared__ __align__(16) float Pb[8][GVS];

    const int qt = blockIdx.x, h = blockIdx.y, b = blockIdx.z;
    const int t = threadIdx.x;
    const int q0 = qt * 64;

    for (int idx = t; idx < 64 * 16; idx += 256) {
        int r = idx >> 4, c4 = (idx & 15) << 2;
        float4 v = *(const float4*)(q + ((size_t)(b*SEQ + q0 + r)) * DM + h*HD + c4);
        *(float4*)(Qs + r * GQS + c4) = v;
    }
    for (int idx = t; idx < 32 * 16; idx += 256) {
        int r = idx >> 4, c4 = (idx & 15) << 2;
        float4 kk = *(const float4*)(kv + ((size_t)(b*NA + r)) * (2*DM) + h*HD + c4);
        *(float4*)(Ks + r * GQS + c4) = kk;
    }
    // V transposed: 2 passes, lanes span keys
#pragma unroll
    for (int pass = 0; pass < 2; pass++) {
        int r  = t & 31;                                // key 0..31
        int c4 = (((t >> 5) + 8 * pass)) << 2;          // dim
        float4 vv = *(const float4*)(kv + ((size_t)(b*NA + r)) * (2*DM) + DM + h*HD + c4);
        Vt[(c4+0) * GVS + r] = vv.x;
        Vt[(c4+1) * GVS + r] = vv.y;
        Vt[(c4+2) * GVS + r] = vv.z;
        Vt[(c4+3) * GVS + r] = vv.w;
    }
    __syncthreads();

    const int warp = t >> 5, lane = t & 31;
    for (int iq = warp * 8; iq < warp * 8 + 8; iq++) {
        const float4* qr4 = (const float4*)(Qs + iq * GQS);
        const float4* kr4 = (const float4*)(Ks + lane * GQS);
        float s = 0.f;
#pragma unroll
        for (int d = 0; d < 16; d++) {
            float4 q4 = qr4[d], k4 = kr4[d];
            s += q4.x*k4.x + q4.y*k4.y + q4.z*k4.z + q4.w*k4.w;
        }
        s *= 0.125f;
        float smax = s;
#pragma unroll
        for (int o = 16; o; o >>= 1) smax = fmaxf(smax, __shfl_xor_sync(0xffffffffu, smax, o));
        float e = expf(s - smax);
        float ssum = e;
#pragma unroll
        for (int o = 16; o; o >>= 1) ssum += __shfl_xor_sync(0xffffffffu, ssum, o);
        Pb[warp][lane] = e;
        __syncwarp();

        float o0 = 0.f, o1 = 0.f;
        const float* va = Vt + lane * GVS;
        const float* vb = Vt + (lane + 32) * GVS;
#pragma unroll
        for (int j4 = 0; j4 < 32; j4 += 4) {
            float4 p  = *(const float4*)(&Pb[warp][j4]);
            float4 a4 = *(const float4*)(va + j4);
            float4 b4 = *(const float4*)(vb + j4);
            o0 += p.x*a4.x + p.y*a4.y + p.z*a4.z + p.w*a4.w;
            o1 += p.x*b4.x + p.y*b4.y + p.z*b4.z + p.w*b4.w;
        }
        const float inv = 1.0f / ssum;
        float* dst = out + ((size_t)(b*SEQ + q0 + iq)) * DM + h*HD;
        dst[lane]      = o0 * inv;
        dst[lane + 32] = o1 * inv;
        __syncwarp();
    }
}

// ---------------- layernorm ----------------
__global__ __launch_bounds__(128)
void ln_kernel(const float* __restrict__ x, const float* __restrict__ g,
               const float* __restrict__ be, float* __restrict__ out)
{
    __shared__ float red[8];
    const int row = blockIdx.x;
    const int t = threadIdx.x;
    float4 v = ((const float4*)(x + (size_t)row * DM))[t];
    float s  = v.x + v.y + v.z + v.w;
    float ss = v.x*v.x + v.y*v.y + v.z*v.z + v.w*v.w;
#pragma unroll
    for (int o = 16; o; o >>= 1) {
        s  += __shfl_xor_sync(0xffffffffu, s, o);
        ss += __shfl_xor_sync(0xffffffffu, ss, o);
    }
    const int warp = t >> 5, lane = t & 31;
    if (lane == 0) { red[warp] = s; red[warp + 4] = ss; }
    __syncthreads();
    if (t == 0) {
        red[0] = red[0] + red[1] + red[2] + red[3];
        red[4] = red[4] + red[5] + red[6] + red[7];
    }
    __syncthreads();
    float mu  = red[0] * (1.0f / DM);
    float var = red[4] * (1.0f / DM) - mu * mu;
    float inv = rsqrtf(var + 1e-5f);
    float4 gg = ((const float4*)g)[t];
    float4 bb = ((const float4*)be)[t];
    float4 o;
    o.x = (v.x - mu) * inv * gg.x + bb.x;
    o.y = (v.y - mu) * inv * gg.y + bb.y;
    o.z = (v.z - mu) * inv * gg.z + bb.z;
    o.w = (v.w - mu) * inv * gg.w + bb.w;
    ((float4*)(out + (size_t)row * DM))[t] = o;
}

// ---------------- launch ----------------
extern "C" void kernel_launch(void* const* d_in, const int* in_sizes, int n_in,
                              void* d_out, int out_size)
{
    const float* x      = (const float*)d_in[0];
    const float* anchors= (const float*)d_in[1];
    const float* lw_in  = (const float*)d_in[2];
    const float* lb_in  = (const float*)d_in[3];
    const float* lw_out = (const float*)d_in[4];
    const float* lb_out = (const float*)d_in[5];
    const float* gw_in  = (const float*)d_in[6];
    const float* gb_in  = (const float*)d_in[7];
    const float* gw_out = (const float*)d_in[8];
    const float* gb_out = (const float*)d_in[9];
    const float* w1     = (const float*)d_in[10];
    const float* b1     = (const float*)d_in[11];
    const float* w2     = (const float*)d_in[12];
    const float* b2     = (const float*)d_in[13];
    const float* g1     = (const float*)d_in[14];
    const float* be1    = (const float*)d_in[15];
    const float* g2     = (const float*)d_in[16];
    const float* be2    = (const float*)d_in[17];
    float* out = (float*)d_out;

    float *qkv, *attn, *x1, *q2, *kv2, *x2, *x3, *hbuf;
    __half* wth;
    cudaGetSymbolAddress((void**)&qkv,  g_qkv);
    cudaGetSymbolAddress((void**)&attn, g_attn);
    cudaGetSymbolAddress((void**)&x1,   g_x1);
    cudaGetSymbolAddress((void**)&q2,   g_q2);
    cudaGetSymbolAddress((void**)&kv2,  g_kv2);
    cudaGetSymbolAddress((void**)&x2,   g_x2);
    cudaGetSymbolAddress((void**)&x3,   g_x3);
    cudaGetSymbolAddress((void**)&hbuf, g_h);
    cudaGetSymbolAddress((void**)&wth,  g_wth);

    const int smem_local = LA_SMEM_F * (int)sizeof(float);
    const int gemm_smem  = GEMM_SMEM_W * (int)sizeof(uint32_t);
    cudaFuncSetAttribute(local_attn_kernel, cudaFuncAttributeMaxDynamicSharedMemorySize, smem_local);
    cudaFuncSetAttribute(gemm_h<false>, cudaFuncAttributeMaxDynamicSharedMemorySize, gemm_smem);
    cudaFuncSetAttribute(gemm_h<true>,  cudaFuncAttributeMaxDynamicSharedMemorySize, gemm_smem);

    dim3 thr(256);

    // [0] weight fp16 pre-round (one launch)
    cvt_all<<<(WTF_TOTAL + 255) / 256, 256>>>(lw_in, lw_out, gw_in, gw_out, w1, w2, wth);
    // [1] anchor k,v projection
    gemm_h<false><<<dim3(1024/256, MAROWS/128), thr, gemm_smem>>>(
        anchors, wth + OFF_GWIN + 512*512, gb_in + 512, nullptr, kv2, MAROWS, 2*DM, DM);
    // [2] local QKV projection
    gemm_h<false><<<dim3(1536/256, MROWS/128), thr, gemm_smem>>>(
        x, wth + OFF_LWIN, lb_in, nullptr, qkv, MROWS, 3*DM, DM);
    // [3] windowed causal attention (vectorized SIMT)
    local_attn_kernel<<<dim3(SEQ/64, NH, BATCH), thr, smem_local>>>(qkv, attn);
    // [4] local out-proj + residual(x) -> x1
    gemm_h<false><<<dim3(DM/256, MROWS/128), thr, gemm_smem>>>(
        attn, wth + OFF_LWOUT, lb_out, x, x1, MROWS, DM, DM);
    // [5] global q projection of x1   <-- ncu capture target (launch #6)
    gemm_h<false><<<dim3(DM/256, MROWS/128), thr, gemm_smem>>>(
        x1, wth + OFF_GWIN, gb_in, nullptr, q2, MROWS, DM, DM);
    // [6] global attention (32 keys)
    global_attn_kernel<<<dim3(SEQ/64, NH, BATCH), thr>>>(q2, kv2, attn);
    // [7] global out-proj + residual(x1) -> x2
    gemm_h<false><<<dim3(DM/256, MROWS/128), thr, gemm_smem>>>(
        attn, wth + OFF_GWOUT, gb_out, x1, x2, MROWS, DM, DM);
    // [8] LN1 -> x3
    ln_kernel<<<MROWS, 128>>>(x2, g1, be1, x3);
    // [9] FFN1 + exact GELU
    gemm_h<true><<<dim3(FF/256, MROWS/128), thr, gemm_smem>>>(
        x3, wth + OFF_W1, b1, nullptr, hbuf, MROWS, FF, DM);
    // [10] FFN2 + residual(x3) -> x2
    gemm_h<false><<<dim3(DM/256, MROWS/128), thr, gemm_smem>>>(
        hbuf, wth + OFF_W2, b2, x3, x2, MROWS, DM, FF);
    // [11] LN2 -> out
    ln_kernel<<<MROWS, 128>>>(x2, g2, be2, out);
}